// round 4
// baseline (speedup 1.0000x reference)
#include <cuda_runtime.h>

#define ROWS_REAL 9800          // 2 * 70 * 70 padded-grid rows
#define ROWS_PAD  9856          // 154 * 64
#define CIN       256
#define NOUT      768           // q | kf | vf packed

__device__ float g_xp[ROWS_PAD * CIN];
__device__ float g_wcat[CIN * NOUT];
__device__ float g_C[ROWS_PAD * NOUT];
__device__ float g_bwin[49 * 256];      // transposed bias window table [j][c]

// ---------------- helpers ----------------
__device__ __forceinline__ int reflect64(int i) {
    if (i < 0) i = -i - 1;
    if (i > 63) i = 127 - i;
    return i;
}
__device__ __forceinline__ void fma2(unsigned long long& d, unsigned long long a, unsigned long long b) {
    asm("fma.rn.f32x2 %0, %1, %2, %0;" : "+l"(d) : "l"(a), "l"(b));
}
__device__ __forceinline__ unsigned long long pk2(float x, float y) {
    unsigned long long r;
    asm("mov.b64 %0, {%1, %2};" : "=l"(r) : "f"(x), "f"(y));
    return r;
}
__device__ __forceinline__ float2 upk2(unsigned long long v) {
    float2 f;
    asm("mov.b64 {%0, %1}, %2;" : "=f"(f.x), "=f"(f.y) : "l"(v));
    return f;
}
__device__ __forceinline__ float ex2f(float x) {
    float r;
    asm("ex2.approx.ftz.f32 %0, %1;" : "=f"(r) : "f"(x));
    return r;
}

// ---------------- prep: padded input gather ----------------
__global__ void prep_xp_kernel(const float* __restrict__ x) {
    int idx = blockIdx.x * blockDim.x + threadIdx.x;
    if (idx >= ROWS_PAD * 64) return;
    int r  = idx >> 6;
    int c4 = (idx & 63) << 2;
    float4 v;
    if (r < ROWS_REAL) {
        int b   = r / 4900;
        int rem = r - b * 4900;
        int hp  = rem / 70;
        int wp  = rem - hp * 70;
        int hs  = reflect64(hp - 3);
        int ws  = reflect64(wp - 3);
        v = *(const float4*)(x + ((((b << 6) + hs) << 6) + ws) * 256 + c4);
    } else {
        v = make_float4(0.f, 0.f, 0.f, 0.f);
    }
    *(float4*)(g_xp + r * 256 + c4) = v;
}

// ---------------- prep: pack weights [256, 768] ----------------
__global__ void prep_w_kernel(const float* __restrict__ wq,
                              const float* __restrict__ wk,
                              const float* __restrict__ wv) {
    int idx = blockIdx.x * blockDim.x + threadIdx.x;
    if (idx >= CIN * NOUT) return;
    int r = idx / 768;
    int c = idx - r * 768;
    int sel = c >> 8;
    int cc  = c & 255;
    const float* w = (sel == 0) ? wq : (sel == 1 ? wk : wv);
    g_wcat[idx] = w[r * 256 + cc];
}

// ---------------- prep: transposed bias window table Bwin[j][c] ----------------
// Window element j of output channel c corresponds to u = c*49 + j:
//   tap = u>>8, ch = u&255; bias = ch<128 ? rh[kh][ch] : rw[kw][ch-128]
__global__ void prep_bwin_kernel(const float* __restrict__ rh,
                                 const float* __restrict__ rw) {
    int idx = blockIdx.x * blockDim.x + threadIdx.x;
    if (idx >= 49 * 256) return;
    int j = idx >> 8;
    int c = idx & 255;
    int u = c * 49 + j;
    int ch = u & 255;
    int tap = u >> 8;
    int kh = (tap * 37) >> 8;
    int kw = tap - kh * 7;
    g_bwin[idx] = (ch < 128) ? rh[kh * 128 + ch] : rw[kw * 128 + (ch - 128)];
}

// ---------------- SGEMM: C[9856,768] = xp * Wcat ----------------
// BM=64 BN=128 BK=16, 256 thr, TM=4 TN=8, A pre-dup float2, double buffer, occ 3.
#define BM 64
#define BN 128
#define BK 16

__global__ __launch_bounds__(256, 3) void sgemm_kernel() {
    __shared__ float2 As[2][BK][BM];   // (a,a) packed: 16 KB
    __shared__ float  Bs[2][BK][BN];   // 16 KB

    int tid = threadIdx.x;
    int tx = tid & 15, ty = tid >> 4;
    int col0 = blockIdx.x * BN;
    int row0 = blockIdx.y * BM;

    int aRow = tid >> 2;              // 0..63
    int aC4  = tid & 3;               // float4 idx within 16-float k-slice
    int bRow = tid >> 4;              // 0..15
    int bC4  = (tid & 15) * 2;

    const float4* Ag4 = (const float4*)g_xp + (row0 + aRow) * 64 + aC4;
    const float4* Bg4 = (const float4*)g_wcat + bRow * 192 + (col0 >> 2) + bC4;

    float4 a0 = Ag4[0];
    float4 b0 = Bg4[0], b1 = Bg4[1];
    {
        int kb = aC4 * 4;
        As[0][kb + 0][aRow] = make_float2(a0.x, a0.x);
        As[0][kb + 1][aRow] = make_float2(a0.y, a0.y);
        As[0][kb + 2][aRow] = make_float2(a0.z, a0.z);
        As[0][kb + 3][aRow] = make_float2(a0.w, a0.w);
        *(float4*)&Bs[0][bRow][bC4 * 4]     = b0;
        *(float4*)&Bs[0][bRow][bC4 * 4 + 4] = b1;
    }
    __syncthreads();

    unsigned long long acc[4][4];
#pragma unroll
    for (int i = 0; i < 4; i++)
#pragma unroll
        for (int j = 0; j < 4; j++) acc[i][j] = 0ULL;

    for (int kt = 0; kt < 16; kt++) {
        int buf = kt & 1;
        if (kt < 15) {
            a0 = Ag4[(kt + 1) * 4];
            b0 = Bg4[(kt + 1) * 3072];
            b1 = Bg4[(kt + 1) * 3072 + 1];
        }
#pragma unroll
        for (int kk = 0; kk < BK; kk++) {
            ulonglong2 aP = *(const ulonglong2*)&As[buf][kk][ty * 4 + 0];
            ulonglong2 aQ = *(const ulonglong2*)&As[buf][kk][ty * 4 + 2];
            float4 bf0 = *(const float4*)&Bs[buf][kk][tx * 8];
            float4 bf1 = *(const float4*)&Bs[buf][kk][tx * 8 + 4];
            unsigned long long bp0 = pk2(bf0.x, bf0.y);
            unsigned long long bp1 = pk2(bf0.z, bf0.w);
            unsigned long long bp2 = pk2(bf1.x, bf1.y);
            unsigned long long bp3 = pk2(bf1.z, bf1.w);
            fma2(acc[0][0], aP.x, bp0); fma2(acc[0][1], aP.x, bp1);
            fma2(acc[0][2], aP.x, bp2); fma2(acc[0][3], aP.x, bp3);
            fma2(acc[1][0], aP.y, bp0); fma2(acc[1][1], aP.y, bp1);
            fma2(acc[1][2], aP.y, bp2); fma2(acc[1][3], aP.y, bp3);
            fma2(acc[2][0], aQ.x, bp0); fma2(acc[2][1], aQ.x, bp1);
            fma2(acc[2][2], aQ.x, bp2); fma2(acc[2][3], aQ.x, bp3);
            fma2(acc[3][0], aQ.y, bp0); fma2(acc[3][1], aQ.y, bp1);
            fma2(acc[3][2], aQ.y, bp2); fma2(acc[3][3], aQ.y, bp3);
        }
        if (kt < 15) {
            int nb = buf ^ 1;
            int kb = aC4 * 4;
            As[nb][kb + 0][aRow] = make_float2(a0.x, a0.x);
            As[nb][kb + 1][aRow] = make_float2(a0.y, a0.y);
            As[nb][kb + 2][aRow] = make_float2(a0.z, a0.z);
            As[nb][kb + 3][aRow] = make_float2(a0.w, a0.w);
            *(float4*)&Bs[nb][bRow][bC4 * 4]     = b0;
            *(float4*)&Bs[nb][bRow][bC4 * 4 + 4] = b1;
            __syncthreads();
        }
    }

#pragma unroll
    for (int i = 0; i < 4; i++) {
        float* cp = g_C + (row0 + ty * 4 + i) * 768 + col0 + tx * 8;
        float2 f0 = upk2(acc[i][0]);
        float2 f1 = upk2(acc[i][1]);
        float2 f2 = upk2(acc[i][2]);
        float2 f3 = upk2(acc[i][3]);
        *(float4*)cp       = make_float4(f0.x, f0.y, f1.x, f1.y);
        *(float4*)(cp + 4) = make_float4(f2.x, f2.y, f3.x, f3.y);
    }
}

// ---------------- attention: 2x2 spatial tile, branchless 2-base windows ----------------
// Window of 49 u's spans at most 2 taps: addr = (j < n1 ? baseA : baseB) + j.
// Bias window comes from transposed global table (coalesced, L1-resident).
__global__ __launch_bounds__(512, 1) void attn_kernel(float* __restrict__ out) {
    extern __shared__ float sm[];          // 64 rows x [K 256f | V 256f] = 32768 floats

    int t = threadIdx.x;
    int bid = blockIdx.x;
    int w2 = bid & 31, h2 = (bid >> 5) & 31, b = bid >> 10;
    int h0 = h2 * 2, w0 = w2 * 2;

    const float4* C4 = (const float4*)g_C;
    float4* sm4 = (float4*)sm;

    // stage K+V tile: 8192 float4s (which=0 K, which=1 V), interleaved rows
#pragma unroll
    for (int i = 0; i < 16; i++) {
        int idx = i * 512 + t;
        int which = idx >> 12;
        int rr = (idx >> 6) & 63;
        int ch4 = idx & 63;
        int rr8 = rr >> 3, rc = rr & 7;
        int grow = (b * 70 + h0 + rr8) * 70 + (w0 + rc);
        sm4[rr * 128 + (which << 6) + ch4] = C4[grow * 192 + 64 + (which << 6) + ch4];
    }
    __syncthreads();

    int slot = t >> 8;
    int c = t & 255;
    int u0 = c * 49;
    int tap0 = u0 >> 8;
    int ch0 = u0 & 255;
    int kh0 = (tap0 * 37) >> 8;            // tap0 / 7
    int kw0 = tap0 - kh0 * 7;
    int n1 = 256 - ch0; if (n1 > 49) n1 = 49;
    int kh1 = kh0, kw1 = kw0 + 1;
    if (kw1 == 7) { kw1 = 0; kh1++; }

    // bias window: 49 coalesced LDGs from transposed table
    float breg[49];
#pragma unroll
    for (int j = 0; j < 49; j++)
        breg[j] = __ldg(&g_bwin[j * 256 + c]);

#pragma unroll
    for (int p = 0; p < 2; p++) {
        int posid = slot * 2 + p;
        int dh = posid >> 1, dw = posid & 1;
        float q = g_C[((b * 70 + h0 + dh + 3) * 70 + (w0 + dw + 3)) * 768 + c];
        float ql2 = q * 1.4426950408889634f;

        int baseA = (((dh + kh0) << 3) + dw + kw0) * 512 + ch0;
        int baseB = (((dh + kh1) << 3) + dw + kw1) * 512 - n1;

        float s0 = 0.f, s1 = 0.f, a0 = 0.f, a1 = 0.f;
#pragma unroll
        for (int j = 0; j < 49; j++) {
            int a = (j < n1) ? baseA : baseB;
            float kv = sm[a + j];
            float vv = sm[a + j + 256];
            float e = ex2f(ql2 * kv);
            if (j & 1) { s1 += e; a1 += e * (vv + breg[j]); }
            else       { s0 += e; a0 += e * (vv + breg[j]); }
        }
        out[((b * 64 + h0 + dh) * 64 + (w0 + dw)) * 256 + c] = (a0 + a1) / (s0 + s1);
    }
}

// ---------------- launch ----------------
extern "C" void kernel_launch(void* const* d_in, const int* in_sizes, int n_in,
                              void* d_out, int out_size) {
    const float* x  = (const float*)d_in[0];
    const float* wq = (const float*)d_in[1];
    const float* wk = (const float*)d_in[2];
    const float* wv = (const float*)d_in[3];
    const float* rh = (const float*)d_in[4];
    const float* rw = (const float*)d_in[5];
    float* out = (float*)d_out;

    prep_xp_kernel<<<(ROWS_PAD * 64 + 255) / 256, 256>>>(x);
    prep_w_kernel<<<(CIN * NOUT + 255) / 256, 256>>>(wq, wk, wv);
    prep_bwin_kernel<<<49, 256>>>(rh, rw);

    dim3 ggrid(6, 154);   // BN tiles x BM tiles
    sgemm_kernel<<<ggrid, 256>>>();

    cudaFuncSetAttribute(attn_kernel,
                         cudaFuncAttributeMaxDynamicSharedMemorySize, 131072);
    attn_kernel<<<2048, 512, 131072>>>(out);
}

// round 6
// speedup vs baseline: 1.6897x; 1.6897x over previous
#include <cuda_runtime.h>
#include <cuda_bf16.h>
#include <cstdint>

#define ROWS_REAL 9800          // 2 * 70 * 70 padded-grid rows
#define ROWS_PAD  9856          // 77 * 128
#define NOUT      768           // q | kf | vf packed
#define K3        768           // split-K: [hi | hi | lo] x [hi | lo | hi]

__device__ __nv_bfloat16 g_A3[ROWS_PAD * K3];   // [row][k3]
__device__ __nv_bfloat16 g_B3[NOUT * K3];       // [n][k3]  (B^T, K-major)
__device__ float g_C[ROWS_PAD * NOUT];          // [q | kf | vf]
__device__ float g_bwin[49 * 256];              // transposed bias window [j][c]

// ---------------- helpers ----------------
__device__ __forceinline__ int reflect64(int i) {
    if (i < 0) i = -i - 1;
    if (i > 63) i = 127 - i;
    return i;
}
__device__ __forceinline__ float ex2f(float x) {
    float r;
    asm("ex2.approx.ftz.f32 %0, %1;" : "=f"(r) : "f"(x));
    return r;
}
__device__ __forceinline__ uint32_t smem_u32(const void* p) {
    uint32_t a;
    asm("{ .reg .u64 t; cvta.to.shared.u64 t, %1; cvt.u32.u64 %0, t; }" : "=r"(a) : "l"(p));
    return a;
}
__device__ __forceinline__ void cp16(uint32_t dst, const void* src) {
    asm volatile("cp.async.cg.shared.global [%0], [%1], 16;" :: "r"(dst), "l"(src));
}
__device__ __forceinline__ void ldsm4(uint32_t* d, uint32_t addr) {
    asm volatile("ldmatrix.sync.aligned.m8n8.x4.shared.b16 {%0,%1,%2,%3}, [%4];"
                 : "=r"(d[0]), "=r"(d[1]), "=r"(d[2]), "=r"(d[3]) : "r"(addr));
}
__device__ __forceinline__ void mma16816(float* c, const uint32_t* a, uint32_t b0, uint32_t b1) {
    asm volatile(
        "mma.sync.aligned.m16n8k16.row.col.f32.bf16.bf16.f32 "
        "{%0,%1,%2,%3}, {%4,%5,%6,%7}, {%8,%9}, {%0,%1,%2,%3};"
        : "+f"(c[0]), "+f"(c[1]), "+f"(c[2]), "+f"(c[3])
        : "r"(a[0]), "r"(a[1]), "r"(a[2]), "r"(a[3]), "r"(b0), "r"(b1));
}

// ---------------- prep: A3 = [hi | hi | lo] of symmetric-padded x, bf16 ----------------
__global__ void prep_a3_kernel(const float* __restrict__ x) {
    int p = blockIdx.x * blockDim.x + threadIdx.x;    // pair index
    if (p >= ROWS_PAD * 384) return;
    int r   = p / 384;
    int kk2 = p - r * 384;
    int k3  = kk2 * 2;
    int seg = k3 >> 8;
    int k   = k3 & 255;
    __nv_bfloat162 o;
    if (r < ROWS_REAL) {
        int b   = r / 4900;
        int rem = r - b * 4900;
        int hp  = rem / 70;
        int wp  = rem - hp * 70;
        int hs  = reflect64(hp - 3);
        int ws  = reflect64(wp - 3);
        const float* src = x + ((((b << 6) + hs) << 6) + ws) * 256;
        float v0 = src[k], v1 = src[k + 1];
        __nv_bfloat16 h0 = __float2bfloat16(v0);
        __nv_bfloat16 h1 = __float2bfloat16(v1);
        if (seg < 2) {
            o.x = h0; o.y = h1;
        } else {
            o.x = __float2bfloat16(v0 - __bfloat162float(h0));
            o.y = __float2bfloat16(v1 - __bfloat162float(h1));
        }
    } else {
        o.x = __float2bfloat16(0.f); o.y = __float2bfloat16(0.f);
    }
    *(__nv_bfloat162*)(g_A3 + r * K3 + k3) = o;
}

// ---------------- prep: B3[n][k3] = [hi | lo | hi] of wcat, bf16 ----------------
__global__ void prep_b3_kernel(const float* __restrict__ wq,
                               const float* __restrict__ wk,
                               const float* __restrict__ wv) {
    int p = blockIdx.x * blockDim.x + threadIdx.x;
    if (p >= NOUT * 384) return;
    int n   = p / 384;
    int kk2 = p - n * 384;
    int k3  = kk2 * 2;
    int seg = k3 >> 8;
    int k   = k3 & 255;
    int sel = n >> 8;
    int cc  = n & 255;
    const float* w = (sel == 0) ? wq : (sel == 1 ? wk : wv);
    float v0 = w[k * 256 + cc];
    float v1 = w[(k + 1) * 256 + cc];
    __nv_bfloat16 h0 = __float2bfloat16(v0);
    __nv_bfloat16 h1 = __float2bfloat16(v1);
    __nv_bfloat162 o;
    if (seg == 1) {
        o.x = __float2bfloat16(v0 - __bfloat162float(h0));
        o.y = __float2bfloat16(v1 - __bfloat162float(h1));
    } else {
        o.x = h0; o.y = h1;
    }
    *(__nv_bfloat162*)(g_B3 + n * K3 + k3) = o;
}

// ---------------- prep: transposed bias window table Bwin[j][c] ----------------
__global__ void prep_bwin_kernel(const float* __restrict__ rh,
                                 const float* __restrict__ rw) {
    int idx = blockIdx.x * blockDim.x + threadIdx.x;
    if (idx >= 49 * 256) return;
    int j = idx >> 8;
    int c = idx & 255;
    int u = c * 49 + j;
    int ch = u & 255;
    int tap = u >> 8;
    int kh = (tap * 37) >> 8;
    int kw = tap - kh * 7;
    g_bwin[idx] = (ch < 128) ? rh[kh * 128 + ch] : rw[kw * 128 + (ch - 128)];
}

// ---------------- mma.sync GEMM: C[9856,768] = A3 . B3^T ----------------
// BM=128 BN=128 BK=32, 8 warps (2x4), warp tile 64x32, 2-stage cp.async pipeline.
// SMEM rows padded to 80B pitch -> ldmatrix phases conflict-free (gcd(5,8)=1).
#define PITCH 80
#define ABYTES (128 * PITCH)    // 10240
#define BUFBYTES (2 * ABYTES)   // 20480 per stage

__global__ __launch_bounds__(256, 2) void mma_gemm_kernel() {
    __shared__ __align__(16) char smem[2 * BUFBYTES];   // 40 KB
    uint32_t sb = smem_u32(smem);

    int tid = threadIdx.x;
    int lane = tid & 31, wid = tid >> 5;
    int wm = wid >> 2, wn = wid & 3;                    // 2 x 4 warp grid
    int row0 = blockIdx.y * 128, col0 = blockIdx.x * 128;

    const __nv_bfloat16* Ag = g_A3 + (size_t)row0 * K3;
    const __nv_bfloat16* Bg = g_B3 + (size_t)col0 * K3;

    int sr  = tid >> 1;             // staged row 0..127
    int sg  = (tid & 1) * 2;        // 16B chunk pair (covers 32B of the 64B row)
    uint32_t stA = sb + sr * PITCH + sg * 16;
    uint32_t stB = stA + ABYTES;

    // ldmatrix lane->address mapping
    int arow = (lane & 7) + (((lane >> 3) & 1) << 3);   // 0..15
    int akc  = (lane >> 4) * 16;                        // k byte offset 0/16
    int brow = (lane & 7) + ((lane >> 4) << 3);         // 0..15
    int bkc  = ((lane >> 3) & 1) * 16;

    float acc[4][4][4];
#pragma unroll
    for (int i = 0; i < 4; i++)
#pragma unroll
        for (int j = 0; j < 4; j++)
#pragma unroll
            for (int v = 0; v < 4; v++) acc[i][j][v] = 0.f;

    // prologue: stage k-chunk 0 into buf 0
    {
        const __nv_bfloat16* a = Ag + sr * K3 + sg * 8;
        const __nv_bfloat16* b = Bg + sr * K3 + sg * 8;
        cp16(stA, a); cp16(stA + 16, a + 8);
        cp16(stB, b); cp16(stB + 16, b + 8);
        asm volatile("cp.async.commit_group;");
    }

    for (int kt = 0; kt < 24; kt++) {
        int buf = kt & 1;
        if (kt < 23) {
            uint32_t off = (buf ^ 1) * BUFBYTES;
            const __nv_bfloat16* a = Ag + sr * K3 + (kt + 1) * 32 + sg * 8;
            const __nv_bfloat16* b = Bg + sr * K3 + (kt + 1) * 32 + sg * 8;
            cp16(stA + off, a); cp16(stA + off + 16, a + 8);
            cp16(stB + off, b); cp16(stB + off + 16, b + 8);
            asm volatile("cp.async.commit_group;");
            asm volatile("cp.async.wait_group 1;");
        } else {
            asm volatile("cp.async.wait_group 0;");
        }
        __syncthreads();

        uint32_t aBase = sb + buf * BUFBYTES;
        uint32_t bBase = aBase + ABYTES;
#pragma unroll
        for (int ks = 0; ks < 2; ks++) {
            uint32_t af[4][4];
#pragma unroll
            for (int mt = 0; mt < 4; mt++)
                ldsm4(af[mt], aBase + (uint32_t)((wm * 64 + mt * 16 + arow) * PITCH + ks * 32 + akc));
            uint32_t bf[2][4];
#pragma unroll
            for (int nh = 0; nh < 2; nh++)
                ldsm4(bf[nh], bBase + (uint32_t)((wn * 32 + nh * 16 + brow) * PITCH + ks * 32 + bkc));
#pragma unroll
            for (int mt = 0; mt < 4; mt++)
#pragma unroll
                for (int nt = 0; nt < 4; nt++)
                    mma16816(acc[mt][nt], af[mt],
                             bf[nt >> 1][(nt & 1) * 2], bf[nt >> 1][(nt & 1) * 2 + 1]);
        }
        __syncthreads();
    }

    // epilogue: m16n8 fragment -> g_C
    int qr = lane >> 2;
    int qc = (lane & 3) * 2;
#pragma unroll
    for (int mt = 0; mt < 4; mt++) {
#pragma unroll
        for (int nt = 0; nt < 4; nt++) {
            int rr = row0 + wm * 64 + mt * 16 + qr;
            int cc = col0 + wn * 32 + nt * 8 + qc;
            *(float2*)(g_C + (size_t)rr * 768 + cc)       = make_float2(acc[mt][nt][0], acc[mt][nt][1]);
            *(float2*)(g_C + (size_t)(rr + 8) * 768 + cc) = make_float2(acc[mt][nt][2], acc[mt][nt][3]);
        }
    }
}

// ---------------- attention: 2x2 spatial tile, branchless 2-base windows ----------------
__global__ __launch_bounds__(512, 1) void attn_kernel(float* __restrict__ out) {
    extern __shared__ float sm[];          // 64 rows x [K 256f | V 256f] = 32768 floats

    int t = threadIdx.x;
    int bid = blockIdx.x;
    int w2 = bid & 31, h2 = (bid >> 5) & 31, b = bid >> 10;
    int h0 = h2 * 2, w0 = w2 * 2;

    const float4* C4 = (const float4*)g_C;
    float4* sm4 = (float4*)sm;

#pragma unroll
    for (int i = 0; i < 16; i++) {
        int idx = i * 512 + t;
        int which = idx >> 12;
        int rr = (idx >> 6) & 63;
        int ch4 = idx & 63;
        int rr8 = rr >> 3, rc = rr & 7;
        int grow = (b * 70 + h0 + rr8) * 70 + (w0 + rc);
        sm4[rr * 128 + (which << 6) + ch4] = C4[grow * 192 + 64 + (which << 6) + ch4];
    }
    __syncthreads();

    int slot = t >> 8;
    int c = t & 255;
    int u0 = c * 49;
    int tap0 = u0 >> 8;
    int ch0 = u0 & 255;
    int kh0 = (tap0 * 37) >> 8;
    int kw0 = tap0 - kh0 * 7;
    int n1 = 256 - ch0; if (n1 > 49) n1 = 49;
    int kh1 = kh0, kw1 = kw0 + 1;
    if (kw1 == 7) { kw1 = 0; kh1++; }

    float breg[49];
#pragma unroll
    for (int j = 0; j < 49; j++)
        breg[j] = __ldg(&g_bwin[j * 256 + c]);

#pragma unroll
    for (int p = 0; p < 2; p++) {
        int posid = slot * 2 + p;
        int dh = posid >> 1, dw = posid & 1;
        float q = g_C[((b * 70 + h0 + dh + 3) * 70 + (w0 + dw + 3)) * 768 + c];
        float ql2 = q * 1.4426950408889634f;

        int baseA = (((dh + kh0) << 3) + dw + kw0) * 512 + ch0;
        int baseB = (((dh + kh1) << 3) + dw + kw1) * 512 - n1;

        float s0 = 0.f, s1 = 0.f, a0 = 0.f, a1 = 0.f;
#pragma unroll
        for (int j = 0; j < 49; j++) {
            int a = (j < n1) ? baseA : baseB;
            float kv = sm[a + j];
            float vv = sm[a + j + 256];
            float e = ex2f(ql2 * kv);
            if (j & 1) { s1 += e; a1 += e * (vv + breg[j]); }
            else       { s0 += e; a0 += e * (vv + breg[j]); }
        }
        out[((b * 64 + h0 + dh) * 64 + (w0 + dw)) * 256 + c] = (a0 + a1) / (s0 + s1);
    }
}

// ---------------- launch ----------------
extern "C" void kernel_launch(void* const* d_in, const int* in_sizes, int n_in,
                              void* d_out, int out_size) {
    const float* x  = (const float*)d_in[0];
    const float* wq = (const float*)d_in[1];
    const float* wk = (const float*)d_in[2];
    const float* wv = (const float*)d_in[3];
    const float* rh = (const float*)d_in[4];
    const float* rw = (const float*)d_in[5];
    float* out = (float*)d_out;

    prep_a3_kernel<<<(ROWS_PAD * 384 + 255) / 256, 256>>>(x);
    prep_b3_kernel<<<(NOUT * 384 + 255) / 256, 256>>>(wq, wk, wv);
    prep_bwin_kernel<<<49, 256>>>(rh, rw);

    dim3 ggrid(6, 77);   // N-tiles x M-tiles
    mma_gemm_kernel<<<ggrid, 256>>>();

    cudaFuncSetAttribute(attn_kernel,
                         cudaFuncAttributeMaxDynamicSharedMemorySize, 131072);
    attn_kernel<<<2048, 512, 131072>>>(out);
}